// round 12
// baseline (speedup 1.0000x reference)
#include <cuda_runtime.h>

typedef unsigned long long ull;
typedef long long ll;

#define HDIM 64
#define GDIM 192  // 3*HDIM
#define MAXT 256
#define MAXB 16384
#define MAXV 102400
#define NTHR 128  // (k-half) x (64 units)
#define ROWS 4    // rows per CTA

#define S_RZ (-1.4426950408889634f)  // -log2(e): r,z gates
#define S_N (2.8853900817779268f)    // 2*log2(e): n gate

// ---------------- device globals (no allocation allowed) ----------------
__device__ int g_tok64;
__device__ int g_pos64;
__device__ int g_hist[256];
__device__ int g_order[MAXB];
__device__ float g_proj[(size_t)MAXV * GDIM];  // (emb @ W_ih^T) * gate-scale

// ---------------- helpers ----------------
__device__ __forceinline__ ull ffma2(ull a, ull b, ull c) {
  ull d;
  asm("fma.rn.f32x2 %0, %1, %2, %3;" : "=l"(d) : "l"(a), "l"(b), "l"(c));
  return d;
}
__device__ __forceinline__ float pair_sum(ull a) {
  unsigned lo, hi;
  asm("mov.b64 {%0, %1}, %2;" : "=r"(lo), "=r"(hi) : "l"(a));
  return __uint_as_float(lo) + __uint_as_float(hi);
}
__device__ __forceinline__ ull mul2s(ull a, float s) {
  unsigned lo, hi;
  asm("mov.b64 {%0, %1}, %2;" : "=r"(lo), "=r"(hi) : "l"(a));
  float x = __uint_as_float(lo) * s, y = __uint_as_float(hi) * s;
  ull d;
  asm("mov.b64 %0, {%1, %2};"
      : "=l"(d)
      : "r"(__float_as_uint(x)), "r"(__float_as_uint(y)));
  return d;
}
__device__ __forceinline__ float rcp_fast(float x) {
  float y;
  asm("rcp.approx.f32 %0, %1;" : "=f"(y) : "f"(x));
  return y;
}
__device__ __forceinline__ float ex2(float x) {
  float y;
  asm("ex2.approx.f32 %0, %1;" : "=f"(y) : "f"(x));
  return y;
}
__device__ __forceinline__ int load_len_(const void* sp, int b, int T, int p64) {
  int v = p64 ? (int)((const ll*)sp)[b] : ((const int*)sp)[b];
  return min(max(v, 1), T);
}
__device__ __forceinline__ int load_tok_(const void* st, ll idx, int t64) {
  return t64 ? (int)((const ll*)st)[idx] : ((const int*)st)[idx];
}

// ---------------- preamble 1: dtype detect + length histogram (1 CTA) -------
__global__ void k_prep(const int* tok, const int* pos, int B, int T) {
  __shared__ int h_sm[256];
  int i = threadIdx.x;
  if (i == 0) {
    int t64 = 1, p64 = 1;
#pragma unroll
    for (int k = 1; k < 32; k += 2) {
      if (tok[k] != 0) t64 = 0;
      if (pos[k] != 0) p64 = 0;
    }
    g_tok64 = t64;
    g_pos64 = p64;
  }
  h_sm[i] = 0;
  __syncthreads();
  int p64 = g_pos64;
  for (int b = i; b < B; b += 256) {
    int v = p64 ? (int)((const ll*)pos)[b] : pos[b];
    int len = min(max(v, 1), T);
    atomicAdd(&h_sm[min(T - len, 255)], 1);  // bin 0 = longest
  }
  __syncthreads();
  g_hist[i] = h_sm[i];
}

// ---------------- preamble 2: scan + scatter (1 CTA) ----------------
__global__ void k_scanscatter(const void* pos, int B, int T) {
  __shared__ int v[256];
  __shared__ int cur[256];
  int i = threadIdx.x;
  int x = g_hist[i];
  v[i] = x;
  __syncthreads();
#pragma unroll
  for (int off = 1; off < 256; off <<= 1) {
    int t = (i >= off) ? v[i - off] : 0;
    __syncthreads();
    v[i] += t;
    __syncthreads();
  }
  cur[i] = v[i] - x;
  __syncthreads();
  int p64 = g_pos64;
  for (int b = i; b < B; b += 256) {
    int len = load_len_(pos, b, T, p64);
    int bin = min(T - len, 255);
    int p = atomicAdd(&cur[bin], 1);
    if (p < MAXB) g_order[p] = b;
  }
}

// ---------------- vocab projection: g_proj = (emb @ W_ih^T) * scale --------
// 128 threads = 2 row-groups x 64 units. Thread (h, jo) holds W_ih rows
// {jo, 64+jo, 128+jo} PRESCALED in registers (96 regs) and computes all 3
// gate outputs for 4 emb rows per iter (group h owns rows 4h..4h+3 of the
// 8-row staged block). LDS:FFMA2 = 1:6 -> fma-bound. cp.async triple buffer
// at prefetch distance 2 (proven R11 pattern).
#define PROJ_RPI 8  // rows staged per iteration (4 per group)
__global__ void __launch_bounds__(NTHR, 3) k_proj(const float* __restrict__ emb,
                                                  const float* __restrict__ W_ih,
                                                  int V) {
  __shared__ __align__(16) float e_sm[3][PROJ_RPI][HDIM];
  const int tid = threadIdx.x;
  const int h = tid >> 6;        // row-group 0/1
  const int jo = tid & 63;       // unit
  const int rbase = h * 4;       // rows rbase..rbase+3 of staged block

  // W rows for unit jo, all 3 gates, prescaled: 192 floats -> 96 ull regs
  ull wr[16], wz[16], wn[16];
  {
    const ulonglong2* p0 = (const ulonglong2*)(W_ih + jo * HDIM);
    const ulonglong2* p1 = (const ulonglong2*)(W_ih + (HDIM + jo) * HDIM);
    const ulonglong2* p2 = (const ulonglong2*)(W_ih + (2 * HDIM + jo) * HDIM);
#pragma unroll
    for (int k = 0; k < 16; k++) {
      ulonglong2 a = p0[k];
      wr[k] = mul2s(a.x, S_RZ);
      // NOTE: 16 iterations cover 32 ulls via two arrays? -> use 2-step below
      (void)a;
    }
  }
  // (re-load cleanly: 32 ull per gate-row is 16 ulonglong2 loads)
  ull wrv[32], wzv[32], wnv[32];
  {
    const ulonglong2* p0 = (const ulonglong2*)(W_ih + jo * HDIM);
    const ulonglong2* p1 = (const ulonglong2*)(W_ih + (HDIM + jo) * HDIM);
    const ulonglong2* p2 = (const ulonglong2*)(W_ih + (2 * HDIM + jo) * HDIM);
#pragma unroll
    for (int k = 0; k < 16; k++) {
      ulonglong2 a = p0[k];
      wrv[2 * k] = mul2s(a.x, S_RZ);
      wrv[2 * k + 1] = mul2s(a.y, S_RZ);
      ulonglong2 b = p1[k];
      wzv[2 * k] = mul2s(b.x, S_RZ);
      wzv[2 * k + 1] = mul2s(b.y, S_RZ);
      ulonglong2 c = p2[k];
      wnv[2 * k] = mul2s(c.x, S_N);
      wnv[2 * k + 1] = mul2s(c.y, S_N);
    }
  }

  int per = (V + gridDim.x - 1) / gridDim.x;
  per = (per + PROJ_RPI - 1) & ~(PROJ_RPI - 1);
  const int vbeg = blockIdx.x * per;
  const int vend = min(vbeg + per, V);
  if (vbeg >= vend) return;
  const int niter = (vend - vbeg + PROJ_RPI - 1) / PROJ_RPI;

  const unsigned smem_base = (unsigned)__cvta_generic_to_shared(e_sm);

  // loaders: all 128 threads, one 16B cp.async each (8 rows x 16 float4)
  const int lrow = tid >> 4, llane = tid & 15;

  auto issue_block = [&](int it, int s) {
    int v = vbeg + it * PROJ_RPI + lrow;
    if (v >= vend) v = vend - 1;  // clamp: data unused, address valid
    unsigned dst =
        smem_base + (unsigned)((s * PROJ_RPI + lrow) * HDIM + llane * 4) * 4u;
    const float* src = emb + (ll)v * HDIM + llane * 4;
    asm volatile("cp.async.cg.shared.global [%0], [%1], 16;" ::"r"(dst),
                 "l"(src));
    asm volatile("cp.async.commit_group;" ::: "memory");
  };

  issue_block(0, 0);
  if (niter > 1) issue_block(1, 1);

  for (int it = 0; it < niter; it++) {
    const int slot = it % 3;
    if (it + 1 < niter)
      asm volatile("cp.async.wait_group 1;" ::: "memory");
    else
      asm volatile("cp.async.wait_group 0;" ::: "memory");
    __syncthreads();

    if (it + 2 < niter)
      issue_block(it + 2, (it + 2) % 3);
    else
      asm volatile("cp.async.commit_group;" ::: "memory");

    // compute: 4 rows x 3 gate outputs for unit jo
    ull ar[4], az[4], an[4];
#pragma unroll
    for (int i = 0; i < 4; i++) {
      ar[i] = 0ull;
      az[i] = 0ull;
      an[i] = 0ull;
    }
#pragma unroll
    for (int k = 0; k < 16; k++) {
#pragma unroll
      for (int i = 0; i < 4; i++) {
        ulonglong2 q = ((const ulonglong2*)e_sm[slot][rbase + i])[k];
        ar[i] = ffma2(wrv[2 * k], q.x, ar[i]);
        ar[i] = ffma2(wrv[2 * k + 1], q.y, ar[i]);
        az[i] = ffma2(wzv[2 * k], q.x, az[i]);
        az[i] = ffma2(wzv[2 * k + 1], q.y, az[i]);
        an[i] = ffma2(wnv[2 * k], q.x, an[i]);
        an[i] = ffma2(wnv[2 * k + 1], q.y, an[i]);
      }
    }
    const int v0 = vbeg + it * PROJ_RPI + rbase;
#pragma unroll
    for (int i = 0; i < 4; i++) {
      if (v0 + i < vend) {
        float* dst = g_proj + (ll)(v0 + i) * GDIM + jo;
        dst[0] = pair_sum(ar[i]);
        dst[64] = pair_sum(az[i]);
        dst[128] = pair_sum(an[i]);
      }
    }
    __syncthreads();  // all reads of `slot` done before overwrite
  }
  asm volatile("cp.async.wait_group 0;" ::: "memory");
}

// ---------------- fused GRU recurrence (R11, unchanged) ----------------
// CTA = 128 threads. kh = (tid>>4)&1 (k-half), j = (tid&15)|((tid>>5)<<4).
// Thread: partial dots (its 32 k's) for 4 rows x 3 gates with PRESCALED W
// (96 regs), shfl.xor(16) combines halves, ex2/rcp gates + h-update for own
// 2 rows. gi values PREFETCHED one full step ahead. One barrier per step.
__global__ void __launch_bounds__(NTHR, 3) k_gru(
    const void* __restrict__ seq_token, const void* __restrict__ seq_pos,
    const float* __restrict__ W_hh, float* __restrict__ out, int B, int T) {
  __shared__ int tok_sm[ROWS][MAXT];  // byte offsets: tok * GDIM * 4
  __shared__ __align__(16) float h_sm[2][ROWS][2][36];  // [buf][row][khalf][32+pad]
  __shared__ int s_row[ROWS], s_len[ROWS];

  const int tid = threadIdx.x;
  const int kh = (tid >> 4) & 1;
  const int j = (tid & 15) | ((tid >> 5) << 4);
  const int rA = kh * 2, rB = rA + 1;  // own rows
  const int tok64 = g_tok64;
  const int jh = j >> 5, jl = j & 31;

  if (tid < ROWS) {
    int idx = ROWS * blockIdx.x + tid;
    int row = (idx < B) ? g_order[idx] : -1;
    s_row[tid] = row;
    s_len[tid] = (row >= 0) ? load_len_(seq_pos, row, T, g_pos64) : 0;
  }
  __syncthreads();
  int tmax = max(max(s_len[0], s_len[1]), max(s_len[2], s_len[3]));
  int tsteps = (tmax + 1) & ~1;
  if (tsteps > MAXT - 1) tsteps = MAXT - 1;
  if (tsteps < tmax) tsteps = tmax;
  const int lenA = s_len[rA], lenB = s_len[rB];

  // stage token BYTE offsets into smem (+ zero sentinel for prefetch tail)
#pragma unroll
  for (int r = 0; r < ROWS; r++) {
    int rw = s_row[r];
    for (int i = tid; i < tsteps; i += NTHR) {
      int tk = (rw >= 0 && i < T) ? load_tok_(seq_token, (ll)rw * T + i, tok64) : 0;
      tok_sm[r][i] = tk * (GDIM * 4);
    }
  }
  if (tid < ROWS) tok_sm[tid][tsteps] = 0;  // sentinel

  // W_hh half-rows for unit j, 3 gates, PRESCALED: 96 floats -> 48 ull regs
  ull wr[16], wz[16], wn[16];
  {
    const ulonglong2* p0 = (const ulonglong2*)(W_hh + j * HDIM + kh * 32);
    const ulonglong2* p1 = (const ulonglong2*)(W_hh + (HDIM + j) * HDIM + kh * 32);
    const ulonglong2* p2 = (const ulonglong2*)(W_hh + (2 * HDIM + j) * HDIM + kh * 32);
#pragma unroll
    for (int k = 0; k < 8; k++) {
      ulonglong2 a = p0[k];
      wr[2 * k] = mul2s(a.x, S_RZ);
      wr[2 * k + 1] = mul2s(a.y, S_RZ);
      ulonglong2 b = p1[k];
      wz[2 * k] = mul2s(b.x, S_RZ);
      wz[2 * k + 1] = mul2s(b.y, S_RZ);
      ulonglong2 c = p2[k];
      wn[2 * k] = mul2s(c.x, S_N);
      wn[2 * k + 1] = mul2s(c.y, S_N);
    }
  }

  // init h = 0 in buffer 0 (own-row slots)
  h_sm[0][rA][jh][jl] = 0.0f;
  h_sm[0][rB][jh][jl] = 0.0f;
  __syncthreads();  // tok_sm + h ready

  const char* gbaseJ = (const char*)g_proj + (unsigned)(j * 4);

  // gi for t=0 (own 2 rows x 3 gates)
  float grA, gzA, gnA, grB, gzB, gnB;
  {
    const float* pA = (const float*)(gbaseJ + (unsigned)tok_sm[rA][0]);
    const float* pB = (const float*)(gbaseJ + (unsigned)tok_sm[rB][0]);
    grA = pA[0]; gzA = pA[64]; gnA = pA[128];
    grB = pB[0]; gzB = pB[64]; gnB = pB[128];
  }

// one GRU step: prefetches gi for tt+1, consumes gi of tt, updates h.
#define GRU_STEP(CUR, NXT, tt)                                                 \
  do {                                                                         \
    const float* pA = (const float*)(gbaseJ + (unsigned)tok_sm[rA][(tt) + 1]); \
    const float* pB = (const float*)(gbaseJ + (unsigned)tok_sm[rB][(tt) + 1]); \
    float qrA = pA[0], qzA = pA[64], qnA = pA[128];                            \
    float qrB = pB[0], qzB = pB[64], qnB = pB[128];                            \
    ull acc[ROWS][3];                                                          \
    _Pragma("unroll") for (int r = 0; r < ROWS; r++) {                         \
      acc[r][0] = 0ull;                                                        \
      acc[r][1] = 0ull;                                                        \
      acc[r][2] = 0ull;                                                        \
    }                                                                          \
    _Pragma("unroll") for (int k = 0; k < 8; k++) {                            \
      _Pragma("unroll") for (int r = 0; r < ROWS; r++) {                       \
        ulonglong2 hq = ((const ulonglong2*)h_sm[CUR][r][kh])[k];              \
        acc[r][0] = ffma2(wr[2 * k], hq.x, acc[r][0]);                         \
        acc[r][0] = ffma2(wr[2 * k + 1], hq.y, acc[r][0]);                     \
        acc[r][1] = ffma2(wz[2 * k], hq.x, acc[r][1]);                         \
        acc[r][1] = ffma2(wz[2 * k + 1], hq.y, acc[r][1]);                     \
        acc[r][2] = ffma2(wn[2 * k], hq.x, acc[r][2]);                         \
        acc[r][2] = ffma2(wn[2 * k + 1], hq.y, acc[r][2]);                     \
      }                                                                        \
    }                                                                          \
    float f[ROWS][3];                                                          \
    _Pragma("unroll") for (int r = 0; r < ROWS; r++) {                         \
      _Pragma("unroll") for (int gg = 0; gg < 3; gg++) {                       \
        float p = pair_sum(acc[r][gg]);                                        \
        f[r][gg] = p + __shfl_xor_sync(0xffffffffu, p, 16);                    \
      }                                                                        \
    }                                                                          \
    {                                                                          \
      float rrA = rcp_fast(1.0f + ex2(grA + f[rA][0]));                        \
      float zzA = rcp_fast(1.0f + ex2(gzA + f[rA][1]));                        \
      float nnA = 1.0f - 2.0f * rcp_fast(ex2(gnA + rrA * f[rA][2]) + 1.0f);    \
      float hoA = h_sm[CUR][rA][jh][jl];                                       \
      float hnA = (1.0f - zzA) * nnA + zzA * hoA;                              \
      h_sm[NXT][rA][jh][jl] = ((tt) < lenA) ? hnA : hoA;                       \
      float rrB = rcp_fast(1.0f + ex2(grB + f[rB][0]));                        \
      float zzB = rcp_fast(1.0f + ex2(gzB + f[rB][1]));                        \
      float nnB = 1.0f - 2.0f * rcp_fast(ex2(gnB + rrB * f[rB][2]) + 1.0f);    \
      float hoB = h_sm[CUR][rB][jh][jl];                                       \
      float hnB = (1.0f - zzB) * nnB + zzB * hoB;                              \
      h_sm[NXT][rB][jh][jl] = ((tt) < lenB) ? hnB : hoB;                       \
    }                                                                          \
    grA = qrA; gzA = qzA; gnA = qnA;                                           \
    grB = qrB; gzB = qzB; gnB = qnB;                                           \
    __syncthreads();                                                           \
  } while (0)

  int t = 0;
  for (; t + 1 < tsteps; t += 2) {
    GRU_STEP(0, 1, t);
    GRU_STEP(1, 0, t + 1);
  }
  int fb = 0;
  if (t < tsteps) {  // odd tail
    GRU_STEP(0, 1, t);
    fb = 1;
  }
#undef GRU_STEP

  {
    int row = s_row[rA];
    if (row >= 0) out[(ll)row * HDIM + j] = h_sm[fb][rA][jh][jl];
    row = s_row[rB];
    if (row >= 0) out[(ll)row * HDIM + j] = h_sm[fb][rB][jh][jl];
  }
}

// ---------------- launch ----------------
extern "C" void kernel_launch(void* const* d_in, const int* in_sizes, int n_in,
                              void* d_out, int out_size) {
  const void* tok = d_in[0];
  const void* pos = d_in[1];
  const float* emb = (const float*)d_in[2];
  const float* wih = (const float*)d_in[3];
  const float* whh = (const float*)d_in[4];
  float* out = (float*)d_out;

  const int B = in_sizes[1];
  const int T = in_sizes[0] / (B > 0 ? B : 1);
  int V = in_sizes[2] / HDIM;
  if (V > MAXV) V = MAXV;

  k_prep<<<1, 256>>>((const int*)tok, (const int*)pos, B, T);
  k_scanscatter<<<1, 256>>>(pos, B, T);
  k_proj<<<1184, NTHR>>>(emb, wih, V);

  const int nblk = (B + ROWS - 1) / ROWS;
  k_gru<<<nblk, NTHR>>>(tok, pos, whh, out, B, T);
}

// round 13
// speedup vs baseline: 1.1531x; 1.1531x over previous
#include <cuda_runtime.h>

typedef unsigned long long ull;
typedef long long ll;

#define HDIM 64
#define GDIM 192  // 3*HDIM
#define MAXT 256
#define MAXB 16384
#define MAXV 102400
#define NTHR 128  // (k-half) x (64 units)
#define ROWS 4    // rows per CTA

#define S_RZ (-1.4426950408889634f)  // -log2(e): r,z gates
#define S_N (2.8853900817779268f)    // 2*log2(e): n gate

// ---------------- device globals (no allocation allowed) ----------------
__device__ int g_tok64;
__device__ int g_pos64;
__device__ int g_hist[256];
__device__ int g_order[MAXB];
__device__ float g_proj[(size_t)MAXV * GDIM];  // (emb @ W_ih^T) * gate-scale

// ---------------- helpers ----------------
__device__ __forceinline__ ull ffma2(ull a, ull b, ull c) {
  ull d;
  asm("fma.rn.f32x2 %0, %1, %2, %3;" : "=l"(d) : "l"(a), "l"(b), "l"(c));
  return d;
}
__device__ __forceinline__ float pair_sum(ull a) {
  unsigned lo, hi;
  asm("mov.b64 {%0, %1}, %2;" : "=r"(lo), "=r"(hi) : "l"(a));
  return __uint_as_float(lo) + __uint_as_float(hi);
}
__device__ __forceinline__ ull mul2s(ull a, float s) {
  unsigned lo, hi;
  asm("mov.b64 {%0, %1}, %2;" : "=r"(lo), "=r"(hi) : "l"(a));
  float x = __uint_as_float(lo) * s, y = __uint_as_float(hi) * s;
  ull d;
  asm("mov.b64 %0, {%1, %2};"
      : "=l"(d)
      : "r"(__float_as_uint(x)), "r"(__float_as_uint(y)));
  return d;
}
__device__ __forceinline__ float rcp_fast(float x) {
  float y;
  asm("rcp.approx.f32 %0, %1;" : "=f"(y) : "f"(x));
  return y;
}
__device__ __forceinline__ float ex2(float x) {
  float y;
  asm("ex2.approx.f32 %0, %1;" : "=f"(y) : "f"(x));
  return y;
}
__device__ __forceinline__ int load_len_(const void* sp, int b, int T, int p64) {
  int v = p64 ? (int)((const ll*)sp)[b] : ((const int*)sp)[b];
  return min(max(v, 1), T);
}
__device__ __forceinline__ int load_tok_(const void* st, ll idx, int t64) {
  return t64 ? (int)((const ll*)st)[idx] : ((const int*)st)[idx];
}

// ---------------- preamble 1: dtype detect + length histogram (1 CTA) -------
__global__ void k_prep(const int* tok, const int* pos, int B, int T) {
  __shared__ int h_sm[256];
  int i = threadIdx.x;
  if (i == 0) {
    int t64 = 1, p64 = 1;
#pragma unroll
    for (int k = 1; k < 32; k += 2) {
      if (tok[k] != 0) t64 = 0;
      if (pos[k] != 0) p64 = 0;
    }
    g_tok64 = t64;
    g_pos64 = p64;
  }
  h_sm[i] = 0;
  __syncthreads();
  int p64 = g_pos64;
  for (int b = i; b < B; b += 256) {
    int v = p64 ? (int)((const ll*)pos)[b] : pos[b];
    int len = min(max(v, 1), T);
    atomicAdd(&h_sm[min(T - len, 255)], 1);  // bin 0 = longest
  }
  __syncthreads();
  g_hist[i] = h_sm[i];
}

// ---------------- preamble 2: scan + scatter (1 CTA) ----------------
__global__ void k_scanscatter(const void* pos, int B, int T) {
  __shared__ int v[256];
  __shared__ int cur[256];
  int i = threadIdx.x;
  int x = g_hist[i];
  v[i] = x;
  __syncthreads();
#pragma unroll
  for (int off = 1; off < 256; off <<= 1) {
    int t = (i >= off) ? v[i - off] : 0;
    __syncthreads();
    v[i] += t;
    __syncthreads();
  }
  cur[i] = v[i] - x;
  __syncthreads();
  int p64 = g_pos64;
  for (int b = i; b < B; b += 256) {
    int len = load_len_(pos, b, T, p64);
    int bin = min(T - len, 255);
    int p = atomicAdd(&cur[bin], 1);
    if (p < MAXB) g_order[p] = b;
  }
}

// ---------------- vocab projection: g_proj = (emb @ W_ih^T) * scale --------
// k_gru's proven recipe ported: CTA = 128 threads, kh = (tid>>4)&1,
// j = (tid&15)|((tid>>5)<<4). Thread holds HALF W_ih rows {j,64+j,128+j}
// prescaled (96 floats = 48 ull regs), computes partial dots for 4 staged
// emb rows x 3 gates (acc 12 ull), shfl.xor(16) combines halves, thread kh
// writes rows 2kh..2kh+1 x 3 outputs. emb rows staged kh-padded ([2][36])
// via cp.async triple buffer at prefetch distance 2.
#define PROJ_RPI 4
__global__ void __launch_bounds__(NTHR, 3) k_proj(const float* __restrict__ emb,
                                                  const float* __restrict__ W_ih,
                                                  int V) {
  __shared__ __align__(16) float e_sm[3][PROJ_RPI][2][36];  // [slot][row][kh][32+pad]
  const int tid = threadIdx.x;
  const int kh = (tid >> 4) & 1;
  const int j = (tid & 15) | ((tid >> 5) << 4);
  const int rA = kh * 2, rB = rA + 1;  // own output rows within staged block

  // W_ih half-rows for unit j, 3 gates, PRESCALED: 96 floats -> 48 ull regs
  ull wr[16], wz[16], wn[16];
  {
    const ulonglong2* p0 = (const ulonglong2*)(W_ih + j * HDIM + kh * 32);
    const ulonglong2* p1 = (const ulonglong2*)(W_ih + (HDIM + j) * HDIM + kh * 32);
    const ulonglong2* p2 = (const ulonglong2*)(W_ih + (2 * HDIM + j) * HDIM + kh * 32);
#pragma unroll
    for (int k = 0; k < 8; k++) {
      ulonglong2 a = p0[k];
      wr[2 * k] = mul2s(a.x, S_RZ);
      wr[2 * k + 1] = mul2s(a.y, S_RZ);
      ulonglong2 b = p1[k];
      wz[2 * k] = mul2s(b.x, S_RZ);
      wz[2 * k + 1] = mul2s(b.y, S_RZ);
      ulonglong2 c = p2[k];
      wn[2 * k] = mul2s(c.x, S_N);
      wn[2 * k + 1] = mul2s(c.y, S_N);
    }
  }

  int per = (V + gridDim.x - 1) / gridDim.x;
  per = (per + PROJ_RPI - 1) & ~(PROJ_RPI - 1);
  const int vbeg = blockIdx.x * per;
  const int vend = min(vbeg + per, V);
  if (vbeg >= vend) return;
  const int niter = (vend - vbeg + PROJ_RPI - 1) / PROJ_RPI;

  const unsigned smem_base = (unsigned)__cvta_generic_to_shared(e_sm);

  // loaders: threads 0..63 issue one 16B cp.async (4 rows x 16 float4).
  // float4 chunk c of a row maps to [kh' = c>>3][ (c&7)*4 ] in padded layout.
  const int lrow = tid >> 4, lchunk = tid & 15;
  const unsigned lpad_off =
      (unsigned)(((lchunk >> 3) * 36 + (lchunk & 7) * 4) * 4);  // bytes in row

  auto issue_block = [&](int it, int s) {
    if (tid < 64) {
      int v = vbeg + it * PROJ_RPI + lrow;
      if (v >= vend) v = vend - 1;  // clamp: data unused, address valid
      unsigned dst = smem_base +
                     (unsigned)((s * PROJ_RPI + lrow) * 72 * 4) + lpad_off;
      const float* src = emb + (ll)v * HDIM + lchunk * 4;
      asm volatile("cp.async.cg.shared.global [%0], [%1], 16;" ::"r"(dst),
                   "l"(src));
    }
    asm volatile("cp.async.commit_group;" ::: "memory");
  };

  issue_block(0, 0);
  if (niter > 1) issue_block(1, 1);

  for (int it = 0; it < niter; it++) {
    const int slot = it % 3;
    if (it + 1 < niter)
      asm volatile("cp.async.wait_group 1;" ::: "memory");
    else
      asm volatile("cp.async.wait_group 0;" ::: "memory");
    __syncthreads();

    if (it + 2 < niter)
      issue_block(it + 2, (it + 2) % 3);
    else
      asm volatile("cp.async.commit_group;" ::: "memory");

    // partial dots over this thread's k-half: 4 rows x 3 gates
    ull acc[PROJ_RPI][3];
#pragma unroll
    for (int r = 0; r < PROJ_RPI; r++) {
      acc[r][0] = 0ull;
      acc[r][1] = 0ull;
      acc[r][2] = 0ull;
    }
#pragma unroll
    for (int k = 0; k < 8; k++) {
#pragma unroll
      for (int r = 0; r < PROJ_RPI; r++) {
        ulonglong2 q = ((const ulonglong2*)e_sm[slot][r][kh])[k];
        acc[r][0] = ffma2(wr[2 * k], q.x, acc[r][0]);
        acc[r][0] = ffma2(wr[2 * k + 1], q.y, acc[r][0]);
        acc[r][1] = ffma2(wz[2 * k], q.x, acc[r][1]);
        acc[r][1] = ffma2(wz[2 * k + 1], q.y, acc[r][1]);
        acc[r][2] = ffma2(wn[2 * k], q.x, acc[r][2]);
        acc[r][2] = ffma2(wn[2 * k + 1], q.y, acc[r][2]);
      }
    }

    // combine halves with partner lane (lane ^ 16: other kh, same j)
    float f[PROJ_RPI][3];
#pragma unroll
    for (int r = 0; r < PROJ_RPI; r++) {
#pragma unroll
      for (int gg = 0; gg < 3; gg++) {
        float p = pair_sum(acc[r][gg]);
        f[r][gg] = p + __shfl_xor_sync(0xffffffffu, p, 16);
      }
    }

    // thread writes its own 2 rows x 3 gate outputs
    const int v0 = vbeg + it * PROJ_RPI;
    {
      int v = v0 + rA;
      if (v < vend) {
        float* dst = g_proj + (ll)v * GDIM + j;
        dst[0] = f[rA][0];
        dst[64] = f[rA][1];
        dst[128] = f[rA][2];
      }
      v = v0 + rB;
      if (v < vend) {
        float* dst = g_proj + (ll)v * GDIM + j;
        dst[0] = f[rB][0];
        dst[64] = f[rB][1];
        dst[128] = f[rB][2];
      }
    }
    __syncthreads();  // all reads of `slot` done before overwrite
  }
  asm volatile("cp.async.wait_group 0;" ::: "memory");
}

// ---------------- fused GRU recurrence (R11, unchanged) ----------------
// CTA = 128 threads. kh = (tid>>4)&1 (k-half), j = (tid&15)|((tid>>5)<<4).
// Thread: partial dots (its 32 k's) for 4 rows x 3 gates with PRESCALED W
// (96 regs), shfl.xor(16) combines halves, ex2/rcp gates + h-update for own
// 2 rows. gi values PREFETCHED one full step ahead. One barrier per step.
__global__ void __launch_bounds__(NTHR, 3) k_gru(
    const void* __restrict__ seq_token, const void* __restrict__ seq_pos,
    const float* __restrict__ W_hh, float* __restrict__ out, int B, int T) {
  __shared__ int tok_sm[ROWS][MAXT];  // byte offsets: tok * GDIM * 4
  __shared__ __align__(16) float h_sm[2][ROWS][2][36];  // [buf][row][khalf][32+pad]
  __shared__ int s_row[ROWS], s_len[ROWS];

  const int tid = threadIdx.x;
  const int kh = (tid >> 4) & 1;
  const int j = (tid & 15) | ((tid >> 5) << 4);
  const int rA = kh * 2, rB = rA + 1;  // own rows
  const int tok64 = g_tok64;
  const int jh = j >> 5, jl = j & 31;

  if (tid < ROWS) {
    int idx = ROWS * blockIdx.x + tid;
    int row = (idx < B) ? g_order[idx] : -1;
    s_row[tid] = row;
    s_len[tid] = (row >= 0) ? load_len_(seq_pos, row, T, g_pos64) : 0;
  }
  __syncthreads();
  int tmax = max(max(s_len[0], s_len[1]), max(s_len[2], s_len[3]));
  int tsteps = (tmax + 1) & ~1;
  if (tsteps > MAXT - 1) tsteps = MAXT - 1;
  if (tsteps < tmax) tsteps = tmax;
  const int lenA = s_len[rA], lenB = s_len[rB];

  // stage token BYTE offsets into smem (+ zero sentinel for prefetch tail)
#pragma unroll
  for (int r = 0; r < ROWS; r++) {
    int rw = s_row[r];
    for (int i = tid; i < tsteps; i += NTHR) {
      int tk = (rw >= 0 && i < T) ? load_tok_(seq_token, (ll)rw * T + i, tok64) : 0;
      tok_sm[r][i] = tk * (GDIM * 4);
    }
  }
  if (tid < ROWS) tok_sm[tid][tsteps] = 0;  // sentinel

  // W_hh half-rows for unit j, 3 gates, PRESCALED: 96 floats -> 48 ull regs
  ull wr[16], wz[16], wn[16];
  {
    const ulonglong2* p0 = (const ulonglong2*)(W_hh + j * HDIM + kh * 32);
    const ulonglong2* p1 = (const ulonglong2*)(W_hh + (HDIM + j) * HDIM + kh * 32);
    const ulonglong2* p2 = (const ulonglong2*)(W_hh + (2 * HDIM + j) * HDIM + kh * 32);
#pragma unroll
    for (int k = 0; k < 8; k++) {
      ulonglong2 a = p0[k];
      wr[2 * k] = mul2s(a.x, S_RZ);
      wr[2 * k + 1] = mul2s(a.y, S_RZ);
      ulonglong2 b = p1[k];
      wz[2 * k] = mul2s(b.x, S_RZ);
      wz[2 * k + 1] = mul2s(b.y, S_RZ);
      ulonglong2 c = p2[k];
      wn[2 * k] = mul2s(c.x, S_N);
      wn[2 * k + 1] = mul2s(c.y, S_N);
    }
  }

  // init h = 0 in buffer 0 (own-row slots)
  h_sm[0][rA][jh][jl] = 0.0f;
  h_sm[0][rB][jh][jl] = 0.0f;
  __syncthreads();  // tok_sm + h ready

  const char* gbaseJ = (const char*)g_proj + (unsigned)(j * 4);

  // gi for t=0 (own 2 rows x 3 gates)
  float grA, gzA, gnA, grB, gzB, gnB;
  {
    const float* pA = (const float*)(gbaseJ + (unsigned)tok_sm[rA][0]);
    const float* pB = (const float*)(gbaseJ + (unsigned)tok_sm[rB][0]);
    grA = pA[0]; gzA = pA[64]; gnA = pA[128];
    grB = pB[0]; gzB = pB[64]; gnB = pB[128];
  }

// one GRU step: prefetches gi for tt+1, consumes gi of tt, updates h.
#define GRU_STEP(CUR, NXT, tt)                                                 \
  do {                                                                         \
    const float* pA = (const float*)(gbaseJ + (unsigned)tok_sm[rA][(tt) + 1]); \
    const float* pB = (const float*)(gbaseJ + (unsigned)tok_sm[rB][(tt) + 1]); \
    float qrA = pA[0], qzA = pA[64], qnA = pA[128];                            \
    float qrB = pB[0], qzB = pB[64], qnB = pB[128];                            \
    ull acc[ROWS][3];                                                          \
    _Pragma("unroll") for (int r = 0; r < ROWS; r++) {                         \
      acc[r][0] = 0ull;                                                        \
      acc[r][1] = 0ull;                                                        \
      acc[r][2] = 0ull;                                                        \
    }                                                                          \
    _Pragma("unroll") for (int k = 0; k < 8; k++) {                            \
      _Pragma("unroll") for (int r = 0; r < ROWS; r++) {                       \
        ulonglong2 hq = ((const ulonglong2*)h_sm[CUR][r][kh])[k];              \
        acc[r][0] = ffma2(wr[2 * k], hq.x, acc[r][0]);                         \
        acc[r][0] = ffma2(wr[2 * k + 1], hq.y, acc[r][0]);                     \
        acc[r][1] = ffma2(wz[2 * k], hq.x, acc[r][1]);                         \
        acc[r][1] = ffma2(wz[2 * k + 1], hq.y, acc[r][1]);                     \
        acc[r][2] = ffma2(wn[2 * k], hq.x, acc[r][2]);                         \
        acc[r][2] = ffma2(wn[2 * k + 1], hq.y, acc[r][2]);                     \
      }                                                                        \
    }                                                                          \
    float f[ROWS][3];                                                          \
    _Pragma("unroll") for (int r = 0; r < ROWS; r++) {                         \
      _Pragma("unroll") for (int gg = 0; gg < 3; gg++) {                       \
        float p = pair_sum(acc[r][gg]);                                        \
        f[r][gg] = p + __shfl_xor_sync(0xffffffffu, p, 16);                    \
      }                                                                        \
    }                                                                          \
    {                                                                          \
      float rrA = rcp_fast(1.0f + ex2(grA + f[rA][0]));                        \
      float zzA = rcp_fast(1.0f + ex2(gzA + f[rA][1]));                        \
      float nnA = 1.0f - 2.0f * rcp_fast(ex2(gnA + rrA * f[rA][2]) + 1.0f);    \
      float hoA = h_sm[CUR][rA][jh][jl];                                       \
      float hnA = (1.0f - zzA) * nnA + zzA * hoA;                              \
      h_sm[NXT][rA][jh][jl] = ((tt) < lenA) ? hnA : hoA;                       \
      float rrB = rcp_fast(1.0f + ex2(grB + f[rB][0]));                        \
      float zzB = rcp_fast(1.0f + ex2(gzB + f[rB][1]));                        \
      float nnB = 1.0f - 2.0f * rcp_fast(ex2(gnB + rrB * f[rB][2]) + 1.0f);    \
      float hoB = h_sm[CUR][rB][jh][jl];                                       \
      float hnB = (1.0f - zzB) * nnB + zzB * hoB;                              \
      h_sm[NXT][rB][jh][jl] = ((tt) < lenB) ? hnB : hoB;                       \
    }                                                                          \
    grA = qrA; gzA = qzA; gnA = qnA;                                           \
    grB = qrB; gzB = qzB; gnB = qnB;                                           \
    __syncthreads();                                                           \
  } while (0)

  int t = 0;
  for (; t + 1 < tsteps; t += 2) {
    GRU_STEP(0, 1, t);
    GRU_STEP(1, 0, t + 1);
  }
  int fb = 0;
  if (t < tsteps) {  // odd tail
    GRU_STEP(0, 1, t);
    fb = 1;
  }
#undef GRU_STEP

  {
    int row = s_row[rA];
    if (row >= 0) out[(ll)row * HDIM + j] = h_sm[fb][rA][jh][jl];
    row = s_row[rB];
    if (row >= 0) out[(ll)row * HDIM + j] = h_sm[fb][rB][jh][jl];
  }
}

// ---------------- launch ----------------
extern "C" void kernel_launch(void* const* d_in, const int* in_sizes, int n_in,
                              void* d_out, int out_size) {
  const void* tok = d_in[0];
  const void* pos = d_in[1];
  const float* emb = (const float*)d_in[2];
  const float* wih = (const float*)d_in[3];
  const float* whh = (const float*)d_in[4];
  float* out = (float*)d_out;

  const int B = in_sizes[1];
  const int T = in_sizes[0] / (B > 0 ? B : 1);
  int V = in_sizes[2] / HDIM;
  if (V > MAXV) V = MAXV;

  k_prep<<<1, 256>>>((const int*)tok, (const int*)pos, B, T);
  k_scanscatter<<<1, 256>>>(pos, B, T);
  k_proj<<<1184, NTHR>>>(emb, wih, V);

  const int nblk = (B + ROWS - 1) / ROWS;
  k_gru<<<nblk, NTHR>>>(tok, pos, whh, out, B, T);
}